// round 4
// baseline (speedup 1.0000x reference)
#include <cuda_runtime.h>
#include <cstdint>

#define BATCH_ 16
#define SEQ_   2048
#define LIN_   256
#define MENC_  512
#define HD_    1024
#define FMLP_  4096
#define CH_    64
#define NCH_   32
#define ROWS_  (NCH_*BATCH_)

// ---------- scratch (device globals; allocation is forbidden) ----------
__device__ float g_Wx[LIN_*HD_];
__device__ float g_bvec[HD_];
__device__ float g_Bu[(size_t)BATCH_*SEQ_*HD_];
__device__ float g_P0[HD_*HD_];
__device__ float g_P1[HD_*HD_];
__device__ float g_HA[ROWS_*HD_];
__device__ float g_HB[ROWS_*HD_];
__device__ float g_S [ROWS_*HD_];
__device__ float g_Z [BATCH_*HD_];
__device__ float g_HL[BATCH_*HD_];
__device__ float g_T [BATCH_*FMLP_];

#define GF_BIAS   1
#define GF_SADD   2
#define GF_SSTORE 4

// 64x64 tile, 128 threads, 8x4 micro-tile, packed f32x2 FMA, double-buffered.
// A: MxK row-major (lda), B: KxN row-major (ldb=N), C row-major.
// SADD: epilogue += g_Bu[b, c*64+j, :] gathered by row r: b=r&15, c=r>>4.
// SSTORE: also scatter result to scanO at the same (b, c*64+j) location.
template<int F>
__global__ void __launch_bounds__(128)
gemm64(const float* __restrict__ Ap, int lda,
       const float* __restrict__ Bp,
       float* __restrict__ Cp,
       const float* __restrict__ bias,
       const float* __restrict__ scanB,
       float* __restrict__ scanO,
       int N, int K, int jstep)
{
    __shared__ float As[2][16][68];
    __shared__ float Bs[2][16][68];
    const int tid = threadIdx.x;
    const int tm = tid >> 4, tn = tid & 15;
    const int m0 = blockIdx.y * 64, n0 = blockIdx.x * 64;
    const int lar = tid >> 2, lac = (tid & 3) * 4;
    const int lbr = tid >> 4, lbc = (tid & 15) * 4;

    const float* Aload = Ap + (size_t)(m0 + lar) * lda + lac;
    const float* Bload = Bp + (size_t)lbr * N + n0 + lbc;

    unsigned long long acc[4][4];
#pragma unroll
    for (int i = 0; i < 4; i++)
#pragma unroll
        for (int q = 0; q < 4; q++) acc[i][q] = 0ull;

    float4 a0 = *(const float4*)(Aload);
    float4 a1 = *(const float4*)(Aload + (size_t)32 * lda);
    float4 b0 = *(const float4*)(Bload);
    float4 b1 = *(const float4*)(Bload + (size_t)8 * N);
    As[0][lac+0][lar] = a0.x; As[0][lac+1][lar] = a0.y;
    As[0][lac+2][lar] = a0.z; As[0][lac+3][lar] = a0.w;
    As[0][lac+0][lar+32] = a1.x; As[0][lac+1][lar+32] = a1.y;
    As[0][lac+2][lar+32] = a1.z; As[0][lac+3][lar+32] = a1.w;
    *(float4*)&Bs[0][lbr][lbc]   = b0;
    *(float4*)&Bs[0][lbr+8][lbc] = b1;
    __syncthreads();

    int buf = 0;
    for (int kt = 0; kt < K; kt += 16) {
        const bool more = (kt + 16) < K;
        if (more) {
            a0 = *(const float4*)(Aload + kt + 16);
            a1 = *(const float4*)(Aload + (size_t)32 * lda + kt + 16);
            b0 = *(const float4*)(Bload + (size_t)(kt + 16) * N);
            b1 = *(const float4*)(Bload + (size_t)(kt + 24) * N);
        }
#pragma unroll
        for (int k = 0; k < 16; k++) {
            float4 xA = *(const float4*)&As[buf][k][tm * 8];
            float4 xB = *(const float4*)&As[buf][k][tm * 8 + 4];
            float4 yB = *(const float4*)&Bs[buf][k][tn * 4];
            unsigned long long pa[4], pb[4];
            asm("mov.b64 %0,{%1,%2};" : "=l"(pa[0]) : "f"(xA.x), "f"(xA.y));
            asm("mov.b64 %0,{%1,%2};" : "=l"(pa[1]) : "f"(xA.z), "f"(xA.w));
            asm("mov.b64 %0,{%1,%2};" : "=l"(pa[2]) : "f"(xB.x), "f"(xB.y));
            asm("mov.b64 %0,{%1,%2};" : "=l"(pa[3]) : "f"(xB.z), "f"(xB.w));
            asm("mov.b64 %0,{%1,%2};" : "=l"(pb[0]) : "f"(yB.x), "f"(yB.x));
            asm("mov.b64 %0,{%1,%2};" : "=l"(pb[1]) : "f"(yB.y), "f"(yB.y));
            asm("mov.b64 %0,{%1,%2};" : "=l"(pb[2]) : "f"(yB.z), "f"(yB.z));
            asm("mov.b64 %0,{%1,%2};" : "=l"(pb[3]) : "f"(yB.w), "f"(yB.w));
#pragma unroll
            for (int i = 0; i < 4; i++)
#pragma unroll
                for (int q = 0; q < 4; q++)
                    asm("fma.rn.f32x2 %0,%1,%2,%0;"
                        : "+l"(acc[i][q]) : "l"(pa[i]), "l"(pb[q]));
        }
        if (more) {
            const int nb = buf ^ 1;
            As[nb][lac+0][lar] = a0.x; As[nb][lac+1][lar] = a0.y;
            As[nb][lac+2][lar] = a0.z; As[nb][lac+3][lar] = a0.w;
            As[nb][lac+0][lar+32] = a1.x; As[nb][lac+1][lar+32] = a1.y;
            As[nb][lac+2][lar+32] = a1.z; As[nb][lac+3][lar+32] = a1.w;
            *(float4*)&Bs[nb][lbr][lbc]   = b0;
            *(float4*)&Bs[nb][lbr+8][lbc] = b1;
            __syncthreads();
        }
        buf ^= 1;
    }

    float cv[8][4];
#pragma unroll
    for (int i = 0; i < 4; i++)
#pragma unroll
        for (int q = 0; q < 4; q++)
            asm("mov.b64 {%0,%1},%2;"
                : "=f"(cv[2*i][q]), "=f"(cv[2*i+1][q]) : "l"(acc[i][q]));

    const int gc = n0 + tn * 4;
    float4 bb = make_float4(0.f, 0.f, 0.f, 0.f);
    if (F & GF_BIAS) bb = *(const float4*)(bias + gc);
#pragma unroll
    for (int m = 0; m < 8; m++) {
        const int gm = m0 + tm * 8 + m;
        float4 v = make_float4(cv[m][0], cv[m][1], cv[m][2], cv[m][3]);
        if (F & GF_BIAS) { v.x += bb.x; v.y += bb.y; v.z += bb.z; v.w += bb.w; }
        size_t soff = 0;
        if (F & (GF_SADD | GF_SSTORE))
            soff = ((size_t)(gm & 15) * SEQ_ + (size_t)(gm >> 4) * CH_ + jstep) * HD_ + gc;
        if (F & GF_SADD) {
            float4 sv = *(const float4*)(scanB + soff);
            v.x += sv.x; v.y += sv.y; v.z += sv.z; v.w += sv.w;
        }
        *(float4*)(Cp + (size_t)gm * N + gc) = v;
        if (F & GF_SSTORE) *(float4*)(scanO + soff) = v;
    }
}

#define SF_BIAS 1
#define SF_RELU 2
#define SF_ADD  4

// Small-M (<=16) GEMM: per block 16 rows x 64 cols, 256 threads (4 rows/thread).
template<int F>
__global__ void __launch_bounds__(256)
sgemm16(const float* __restrict__ Ap, long lda,
        const float* __restrict__ Bp, int ldb,
        float* __restrict__ Cp, int ldc,
        const float* __restrict__ bias,
        const float* __restrict__ addend, long ldadd,
        int M, int K)
{
    __shared__ float As[16][33];
    const int tid = threadIdx.x;
    const int c = tid & 63, g = tid >> 6;
    const int col = blockIdx.x * 64 + c;
    float acc[4] = {0.f, 0.f, 0.f, 0.f};
    for (int k0 = 0; k0 < K; k0 += 32) {
        __syncthreads();
        for (int e = tid; e < 512; e += 256) {
            const int r = e >> 5, kk = e & 31;
            As[r][kk] = (r < M) ? Ap[(size_t)r * lda + k0 + kk] : 0.f;
        }
        __syncthreads();
#pragma unroll 8
        for (int kk = 0; kk < 32; kk++) {
            const float bv = Bp[(size_t)(k0 + kk) * ldb + col];
#pragma unroll
            for (int i = 0; i < 4; i++) acc[i] += As[g * 4 + i][kk] * bv;
        }
    }
#pragma unroll
    for (int i = 0; i < 4; i++) {
        const int r = g * 4 + i;
        if (r < M) {
            float v = acc[i];
            if (F & SF_BIAS) v += bias[col];
            if (F & SF_ADD)  v += addend[(size_t)r * ldadd + col];
            if (F & SF_RELU) v = fmaxf(v, 0.f);
            Cp[(size_t)r * ldc + col] = v;
        }
    }
}

__global__ void __launch_bounds__(256)
ln16(const float* __restrict__ z, const float* __restrict__ gam,
     const float* __restrict__ bet, float* __restrict__ o)
{
    __shared__ float s1[8], s2[8];
    const int b = blockIdx.x, tid = threadIdx.x;
    float4 v = ((const float4*)(z + (size_t)b * HD_))[tid];
    float s = v.x + v.y + v.z + v.w;
    float q = v.x*v.x + v.y*v.y + v.z*v.z + v.w*v.w;
    for (int d = 16; d > 0; d >>= 1) {
        s += __shfl_xor_sync(0xffffffffu, s, d);
        q += __shfl_xor_sync(0xffffffffu, q, d);
    }
    if ((tid & 31) == 0) { s1[tid >> 5] = s; s2[tid >> 5] = q; }
    __syncthreads();
    if (tid < 8) {
        s = s1[tid]; q = s2[tid];
        for (int d = 4; d > 0; d >>= 1) {
            s += __shfl_xor_sync(0xffu, s, d);
            q += __shfl_xor_sync(0xffu, q, d);
        }
        if (tid == 0) { s1[0] = s; s2[0] = q; }
    }
    __syncthreads();
    const float mu = s1[0] * (1.f / HD_);
    const float var = s2[0] * (1.f / HD_) - mu * mu;
    const float rs = rsqrtf(var + 1e-5f);
    float4 gg = ((const float4*)gam)[tid];
    float4 bb = ((const float4*)bet)[tid];
    float4 r;
    r.x = (v.x - mu) * rs * gg.x + bb.x;
    r.y = (v.y - mu) * rs * gg.y + bb.y;
    r.z = (v.z - mu) * rs * gg.z + bb.z;
    r.w = (v.w - mu) * rs * gg.w + bb.w;
    ((float4*)(o + (size_t)b * HD_))[tid] = r;
}

// phase-1 init: local state at j=0 is just Bu[b, c*64, :]
__global__ void gatherBu(const float* __restrict__ Bu, float* __restrict__ H)
{
    const int r = blockIdx.x;
    const size_t src = ((size_t)(r & 15) * SEQ_ + (size_t)(r >> 4) * CH_) * HD_;
    ((float4*)(H + (size_t)r * HD_))[threadIdx.x] =
        ((const float4*)(Bu + src))[threadIdx.x];
}

__global__ void zero16k(float* p)
{
    ((float4*)p)[blockIdx.x * 256 + threadIdx.x] = make_float4(0.f, 0.f, 0.f, 0.f);
}

extern "C" void kernel_launch(void* const* d_in, const int* in_sizes, int n_in,
                              void* d_out, int out_size)
{
    (void)in_sizes; (void)n_in; (void)out_size;
    const float* x    = (const float*)d_in[0];
    const float* Wenc = (const float*)d_in[1];
    const float* benc = (const float*)d_in[2];
    const float* WB   = (const float*)d_in[3];
    const float* Amat = (const float*)d_in[4];
    const float* Wres = (const float*)d_in[5];
    const float* bres = (const float*)d_in[6];
    const float* lng  = (const float*)d_in[7];
    const float* lnb  = (const float*)d_in[8];
    const float* W1   = (const float*)d_in[9];
    const float* b1   = (const float*)d_in[10];
    const float* W2   = (const float*)d_in[11];
    const float* b2   = (const float*)d_in[12];
    float* out0 = (float*)d_out;                 // (16,1024) MLP head output
    float* outH = out0 + BATCH_ * HD_;           // (16,2048,1024) H_seq_pre

    float *Wx, *bvec, *Bu, *P0, *P1, *HA, *HB, *S, *Z, *HL, *T;
    cudaGetSymbolAddress((void**)&Wx,   g_Wx);
    cudaGetSymbolAddress((void**)&bvec, g_bvec);
    cudaGetSymbolAddress((void**)&Bu,   g_Bu);
    cudaGetSymbolAddress((void**)&P0,   g_P0);
    cudaGetSymbolAddress((void**)&P1,   g_P1);
    cudaGetSymbolAddress((void**)&HA,   g_HA);
    cudaGetSymbolAddress((void**)&HB,   g_HB);
    cudaGetSymbolAddress((void**)&S,    g_S);
    cudaGetSymbolAddress((void**)&Z,    g_Z);
    cudaGetSymbolAddress((void**)&HL,   g_HL);
    cudaGetSymbolAddress((void**)&T,    g_T);

    // 1) Wx = W_enc @ W_B ; bvec = b_enc @ W_B   (algebraic fusion of encoder)
    gemm64<0><<<dim3(16, 4), 128>>>(Wenc, MENC_, WB, Wx,
                                    nullptr, nullptr, nullptr, HD_, MENC_, 0);
    sgemm16<0><<<16, 256>>>(benc, MENC_, WB, HD_, bvec, HD_,
                            nullptr, nullptr, 0, 1, MENC_);

    // 2) Bu = x2d @ Wx + bvec   (32768 x 1024, K=256)
    gemm64<GF_BIAS><<<dim3(16, 512), 128>>>(x, LIN_, Wx, Bu,
                                            bvec, nullptr, nullptr, HD_, LIN_, 0);

    // 3) A^64 via 6 squarings -> P1
    gemm64<0><<<dim3(16,16),128>>>(Amat, HD_, Amat, P0, nullptr,nullptr,nullptr, HD_, HD_, 0);
    gemm64<0><<<dim3(16,16),128>>>(P0,   HD_, P0,   P1, nullptr,nullptr,nullptr, HD_, HD_, 0);
    gemm64<0><<<dim3(16,16),128>>>(P1,   HD_, P1,   P0, nullptr,nullptr,nullptr, HD_, HD_, 0);
    gemm64<0><<<dim3(16,16),128>>>(P0,   HD_, P0,   P1, nullptr,nullptr,nullptr, HD_, HD_, 0);
    gemm64<0><<<dim3(16,16),128>>>(P1,   HD_, P1,   P0, nullptr,nullptr,nullptr, HD_, HD_, 0);
    gemm64<0><<<dim3(16,16),128>>>(P0,   HD_, P0,   P1, nullptr,nullptr,nullptr, HD_, HD_, 0);

    // 4) Phase 1: local scans from zero, all 32 chunks in parallel (rows r=c*16+b)
    gatherBu<<<ROWS_, 256>>>(Bu, HA);
    float* cur = HA; float* nxt = HB;
    for (int j = 1; j < CH_; j++) {
        gemm64<GF_SADD><<<dim3(16, 8), 128>>>(cur, HD_, Amat, nxt,
                                              nullptr, Bu, nullptr, HD_, HD_, j);
        float* t = cur; cur = nxt; nxt = t;
    }
    float* E = cur;  // chunk endpoints E_c (= g_HB after 63 steps)

    // 5) Carries: S_0 = 0; S_{c+1} = S_c @ A^64 + E_c
    zero16k<<<16, 256>>>(S);
    for (int c = 0; c < NCH_ - 1; c++) {
        sgemm16<SF_ADD><<<16, 256>>>(S + (size_t)c * 16 * HD_, HD_, P1, HD_,
                                     S + (size_t)(c + 1) * 16 * HD_, HD_,
                                     nullptr, E + (size_t)c * 16 * HD_, HD_,
                                     16, HD_);
    }

    // 6) Phase 2: true recurrence per chunk from carry-in; scatter H_seq_pre to d_out
    cur = S; nxt = (E == HA) ? HB : HA;
    for (int j = 0; j < CH_; j++) {
        gemm64<GF_SADD | GF_SSTORE><<<dim3(16, 8), 128>>>(cur, HD_, Amat, nxt,
                                                          nullptr, Bu, outH,
                                                          HD_, HD_, j);
        cur = nxt;
        nxt = (cur == HA) ? HB : HA;
    }

    // 7) z = x[:, -1, :] @ W_res + b_res + H_seq_pre[:, -1, :]
    sgemm16<SF_BIAS | SF_ADD><<<16, 256>>>(x + (size_t)(SEQ_ - 1) * LIN_,
                                           (long)SEQ_ * LIN_,
                                           Wres, HD_, Z, HD_, bres,
                                           outH + (size_t)(SEQ_ - 1) * HD_,
                                           (long)SEQ_ * HD_, BATCH_, LIN_);
    // 8) LayerNorm
    ln16<<<BATCH_, 256>>>(Z, lng, lnb, HL);
    // 9) MLP head
    sgemm16<SF_BIAS | SF_RELU><<<FMLP_ / 64, 256>>>(HL, HD_, W1, FMLP_, T, FMLP_,
                                                    b1, nullptr, 0, BATCH_, HD_);
    sgemm16<SF_BIAS><<<HD_ / 64, 256>>>(T, FMLP_, W2, HD_, out0, HD_,
                                        b2, nullptr, 0, BATCH_, FMLP_);
}

// round 5
// speedup vs baseline: 1.6390x; 1.6390x over previous
#include <cuda_runtime.h>
#include <cstdint>

#define BATCH_ 16
#define SEQ_   2048
#define LIN_   256
#define MENC_  512
#define HD_    1024
#define FMLP_  4096
#define CH_    32
#define NCH_   64
#define ROWS_  (NCH_*BATCH_)        // 1024
#define APRON_ 512                  // zero rows in front of F buffers
#define FROWS_ (APRON_ + ROWS_)     // 1536

// ---------- scratch (device globals; allocation is forbidden) ----------
__device__ float g_Wx[LIN_*HD_];
__device__ float g_bvec[HD_];
__device__ float g_Bu[(size_t)BATCH_*SEQ_*HD_];
__device__ float g_P0[HD_*HD_];
__device__ float g_P1[HD_*HD_];
__device__ float g_FA[(size_t)FROWS_*HD_];
__device__ float g_FB[(size_t)FROWS_*HD_];
__device__ float g_Z [BATCH_*HD_];
__device__ float g_HL[BATCH_*HD_];
__device__ float g_T [BATCH_*FMLP_];

#define GF_BIAS   1
#define GF_SADD   2
#define GF_SSTORE 4
#define GF_ADDM   8

// 64x64 tile, 256 threads, 4x4 micro-tile, packed f32x2 FMA (A-pairs come
// straight from LDS.128 as b64 lanes), double-buffered SMEM.
// A: MxK row-major (lda); B: KxN row-major; C row-major (ldc=N).
// GF_SADD : epilogue += Bu[b, c*CH+j, :]  with row r: b=r&15, c=r>>4
// GF_SSTORE: also scatter result to scanO at same (b, c*CH+j)
// GF_ADDM : epilogue += addM[gm*N+gc]
template<int F>
__global__ void __launch_bounds__(256)
gemm64(const float* __restrict__ Ap, int lda,
       const float* __restrict__ Bp,
       float* __restrict__ Cp,
       const float* __restrict__ bias,
       const float* __restrict__ scanB,
       float* __restrict__ scanO,
       const float* __restrict__ addM,
       int N, int K, int jstep)
{
    __shared__ float As[2][16][68];   // [k][m]
    __shared__ float Bs[2][16][68];   // [k][n]
    const int tid = threadIdx.x;
    const int tm = tid >> 4, tn = tid & 15;
    const int m0 = blockIdx.y * 64, n0 = blockIdx.x * 64;
    const int lar = tid >> 2, lac = (tid & 3) * 4;
    const int lbr = tid >> 4, lbc = (tid & 15) * 4;

    const float* Aload = Ap + (size_t)(m0 + lar) * lda + lac;
    const float* Bload = Bp + (size_t)lbr * N + n0 + lbc;

    unsigned long long acc[2][4];
#pragma unroll
    for (int p = 0; p < 2; p++)
#pragma unroll
        for (int q = 0; q < 4; q++) acc[p][q] = 0ull;

    float4 a = *(const float4*)(Aload);
    float4 b = *(const float4*)(Bload);
    As[0][lac+0][lar] = a.x; As[0][lac+1][lar] = a.y;
    As[0][lac+2][lar] = a.z; As[0][lac+3][lar] = a.w;
    *(float4*)&Bs[0][lbr][lbc] = b;
    __syncthreads();

    int buf = 0;
    for (int kt = 0; kt < K; kt += 16) {
        const bool more = (kt + 16) < K;
        if (more) {
            a = *(const float4*)(Aload + kt + 16);
            b = *(const float4*)(Bload + (size_t)(kt + 16) * N);
        }
#pragma unroll
        for (int k = 0; k < 16; k++) {
            const ulonglong2 pa = *(const ulonglong2*)&As[buf][k][tm * 4];
            const float4 bv = *(const float4*)&Bs[buf][k][tn * 4];
            unsigned long long pb0, pb1, pb2, pb3;
            asm("mov.b64 %0,{%1,%1};" : "=l"(pb0) : "f"(bv.x));
            asm("mov.b64 %0,{%1,%1};" : "=l"(pb1) : "f"(bv.y));
            asm("mov.b64 %0,{%1,%1};" : "=l"(pb2) : "f"(bv.z));
            asm("mov.b64 %0,{%1,%1};" : "=l"(pb3) : "f"(bv.w));
            asm("fma.rn.f32x2 %0,%1,%2,%0;" : "+l"(acc[0][0]) : "l"(pa.x), "l"(pb0));
            asm("fma.rn.f32x2 %0,%1,%2,%0;" : "+l"(acc[0][1]) : "l"(pa.x), "l"(pb1));
            asm("fma.rn.f32x2 %0,%1,%2,%0;" : "+l"(acc[0][2]) : "l"(pa.x), "l"(pb2));
            asm("fma.rn.f32x2 %0,%1,%2,%0;" : "+l"(acc[0][3]) : "l"(pa.x), "l"(pb3));
            asm("fma.rn.f32x2 %0,%1,%2,%0;" : "+l"(acc[1][0]) : "l"(pa.y), "l"(pb0));
            asm("fma.rn.f32x2 %0,%1,%2,%0;" : "+l"(acc[1][1]) : "l"(pa.y), "l"(pb1));
            asm("fma.rn.f32x2 %0,%1,%2,%0;" : "+l"(acc[1][2]) : "l"(pa.y), "l"(pb2));
            asm("fma.rn.f32x2 %0,%1,%2,%0;" : "+l"(acc[1][3]) : "l"(pa.y), "l"(pb3));
        }
        if (more) {
            const int nb = buf ^ 1;
            As[nb][lac+0][lar] = a.x; As[nb][lac+1][lar] = a.y;
            As[nb][lac+2][lar] = a.z; As[nb][lac+3][lar] = a.w;
            *(float4*)&Bs[nb][lbr][lbc] = b;
            __syncthreads();
        }
        buf ^= 1;
    }

    float cv[4][4];
#pragma unroll
    for (int p = 0; p < 2; p++)
#pragma unroll
        for (int q = 0; q < 4; q++)
            asm("mov.b64 {%0,%1},%2;"
                : "=f"(cv[2*p][q]), "=f"(cv[2*p+1][q]) : "l"(acc[p][q]));

    const int gc = n0 + tn * 4;
    float4 bb = make_float4(0.f, 0.f, 0.f, 0.f);
    if (F & GF_BIAS) bb = *(const float4*)(bias + gc);
#pragma unroll
    for (int mr = 0; mr < 4; mr++) {
        const int gm = m0 + tm * 4 + mr;
        float4 v = make_float4(cv[mr][0], cv[mr][1], cv[mr][2], cv[mr][3]);
        if (F & GF_BIAS) { v.x += bb.x; v.y += bb.y; v.z += bb.z; v.w += bb.w; }
        if (F & GF_ADDM) {
            float4 av = *(const float4*)(addM + (size_t)gm * N + gc);
            v.x += av.x; v.y += av.y; v.z += av.z; v.w += av.w;
        }
        size_t soff = 0;
        if (F & (GF_SADD | GF_SSTORE))
            soff = ((size_t)(gm & 15) * SEQ_ + (size_t)(gm >> 4) * CH_ + jstep) * HD_ + gc;
        if (F & GF_SADD) {
            float4 sv = *(const float4*)(scanB + soff);
            v.x += sv.x; v.y += sv.y; v.z += sv.z; v.w += sv.w;
        }
        *(float4*)(Cp + (size_t)gm * N + gc) = v;
        if (F & GF_SSTORE) *(float4*)(scanO + soff) = v;
    }
}

#define SF_BIAS 1
#define SF_RELU 2
#define SF_ADD  4

// Small-M (<=16) GEMM: per block 16 rows x 64 cols, 256 threads.
template<int F>
__global__ void __launch_bounds__(256)
sgemm16(const float* __restrict__ Ap, long lda,
        const float* __restrict__ Bp, int ldb,
        float* __restrict__ Cp, int ldc,
        const float* __restrict__ bias,
        const float* __restrict__ addend, long ldadd,
        int M, int K)
{
    __shared__ float As[16][33];
    const int tid = threadIdx.x;
    const int c = tid & 63, g = tid >> 6;
    const int col = blockIdx.x * 64 + c;
    float acc[4] = {0.f, 0.f, 0.f, 0.f};
    for (int k0 = 0; k0 < K; k0 += 32) {
        __syncthreads();
        for (int e = tid; e < 512; e += 256) {
            const int r = e >> 5, kk = e & 31;
            As[r][kk] = (r < M) ? Ap[(size_t)r * lda + k0 + kk] : 0.f;
        }
        __syncthreads();
#pragma unroll 8
        for (int kk = 0; kk < 32; kk++) {
            const float bv = Bp[(size_t)(k0 + kk) * ldb + col];
#pragma unroll
            for (int i = 0; i < 4; i++) acc[i] += As[g * 4 + i][kk] * bv;
        }
    }
#pragma unroll
    for (int i = 0; i < 4; i++) {
        const int r = g * 4 + i;
        if (r < M) {
            float v = acc[i];
            if (F & SF_BIAS) v += bias[col];
            if (F & SF_ADD)  v += addend[(size_t)r * ldadd + col];
            if (F & SF_RELU) v = fmaxf(v, 0.f);
            Cp[(size_t)r * ldc + col] = v;
        }
    }
}

__global__ void __launch_bounds__(256)
ln16(const float* __restrict__ z, const float* __restrict__ gam,
     const float* __restrict__ bet, float* __restrict__ o)
{
    __shared__ float s1[8], s2[8];
    const int b = blockIdx.x, tid = threadIdx.x;
    float4 v = ((const float4*)(z + (size_t)b * HD_))[tid];
    float s = v.x + v.y + v.z + v.w;
    float q = v.x*v.x + v.y*v.y + v.z*v.z + v.w*v.w;
    for (int d = 16; d > 0; d >>= 1) {
        s += __shfl_xor_sync(0xffffffffu, s, d);
        q += __shfl_xor_sync(0xffffffffu, q, d);
    }
    if ((tid & 31) == 0) { s1[tid >> 5] = s; s2[tid >> 5] = q; }
    __syncthreads();
    if (tid < 8) {
        s = s1[tid]; q = s2[tid];
        for (int d = 4; d > 0; d >>= 1) {
            s += __shfl_xor_sync(0xffu, s, d);
            q += __shfl_xor_sync(0xffu, q, d);
        }
        if (tid == 0) { s1[0] = s; s2[0] = q; }
    }
    __syncthreads();
    const float mu = s1[0] * (1.f / HD_);
    const float var = s2[0] * (1.f / HD_) - mu * mu;
    const float rs = rsqrtf(var + 1e-5f);
    float4 gg = ((const float4*)gam)[tid];
    float4 bb = ((const float4*)bet)[tid];
    float4 r;
    r.x = (v.x - mu) * rs * gg.x + bb.x;
    r.y = (v.y - mu) * rs * gg.y + bb.y;
    r.z = (v.z - mu) * rs * gg.z + bb.z;
    r.w = (v.w - mu) * rs * gg.w + bb.w;
    ((float4*)(o + (size_t)b * HD_))[tid] = r;
}

// phase-1 init: local state at j=0 is Bu[b, c*CH, :]
__global__ void gatherBu(const float* __restrict__ Bu, float* __restrict__ H)
{
    const int r = blockIdx.x;
    const size_t src = ((size_t)(r & 15) * SEQ_ + (size_t)(r >> 4) * CH_) * HD_;
    ((float4*)(H + (size_t)r * HD_))[threadIdx.x] =
        ((const float4*)(Bu + src))[threadIdx.x];
}

__global__ void zero4(float* p)
{
    ((float4*)p)[blockIdx.x * 256 + threadIdx.x] = make_float4(0.f, 0.f, 0.f, 0.f);
}

extern "C" void kernel_launch(void* const* d_in, const int* in_sizes, int n_in,
                              void* d_out, int out_size)
{
    (void)in_sizes; (void)n_in; (void)out_size;
    const float* x    = (const float*)d_in[0];
    const float* Wenc = (const float*)d_in[1];
    const float* benc = (const float*)d_in[2];
    const float* WB   = (const float*)d_in[3];
    const float* Amat = (const float*)d_in[4];
    const float* Wres = (const float*)d_in[5];
    const float* bres = (const float*)d_in[6];
    const float* lng  = (const float*)d_in[7];
    const float* lnb  = (const float*)d_in[8];
    const float* W1   = (const float*)d_in[9];
    const float* b1   = (const float*)d_in[10];
    const float* W2   = (const float*)d_in[11];
    const float* b2   = (const float*)d_in[12];
    float* out0 = (float*)d_out;                 // (16,1024) MLP head
    float* outH = out0 + BATCH_ * HD_;           // (16,2048,1024) H_seq_pre

    float *Wx, *bvec, *Bu, *P0, *P1, *FA, *FB, *Z, *HL, *T;
    cudaGetSymbolAddress((void**)&Wx,   g_Wx);
    cudaGetSymbolAddress((void**)&bvec, g_bvec);
    cudaGetSymbolAddress((void**)&Bu,   g_Bu);
    cudaGetSymbolAddress((void**)&P0,   g_P0);
    cudaGetSymbolAddress((void**)&P1,   g_P1);
    cudaGetSymbolAddress((void**)&FA,   g_FA);
    cudaGetSymbolAddress((void**)&FB,   g_FB);
    cudaGetSymbolAddress((void**)&Z,    g_Z);
    cudaGetSymbolAddress((void**)&HL,   g_HL);
    cudaGetSymbolAddress((void**)&T,    g_T);

    const size_t AP = (size_t)APRON_ * HD_;

    // 1) Wx = W_enc @ W_B ; bvec = b_enc @ W_B
    gemm64<0><<<dim3(16, 4), 256>>>(Wenc, MENC_, WB, Wx,
                                    nullptr, nullptr, nullptr, nullptr, HD_, MENC_, 0);
    sgemm16<0><<<16, 256>>>(benc, MENC_, WB, HD_, bvec, HD_,
                            nullptr, nullptr, 0, 1, MENC_);

    // 2) Bu = x2d @ Wx + bvec   (32768 x 1024, K=256)
    gemm64<GF_BIAS><<<dim3(16, 512), 256>>>(x, LIN_, Wx, Bu,
                                            bvec, nullptr, nullptr, nullptr, HD_, LIN_, 0);

    // 3) P0 = A^CH = A^32 via 5 squarings
    gemm64<0><<<dim3(16,16),256>>>(Amat, HD_, Amat, P0, 0,0,0,0, HD_, HD_, 0); // A^2
    gemm64<0><<<dim3(16,16),256>>>(P0,   HD_, P0,   P1, 0,0,0,0, HD_, HD_, 0); // A^4
    gemm64<0><<<dim3(16,16),256>>>(P1,   HD_, P1,   P0, 0,0,0,0, HD_, HD_, 0); // A^8
    gemm64<0><<<dim3(16,16),256>>>(P0,   HD_, P0,   P1, 0,0,0,0, HD_, HD_, 0); // A^16
    gemm64<0><<<dim3(16,16),256>>>(P1,   HD_, P1,   P0, 0,0,0,0, HD_, HD_, 0); // A^32

    // 4) zero aprons (512 rows each buffer)
    zero4<<<512, 256>>>(FA);
    zero4<<<512, 256>>>(FB);

    // 5) Phase 1: local scans from zero, 64 chunks x 16 batch rows in parallel
    gatherBu<<<ROWS_, 256>>>(Bu, FA + AP);
    float* cur = FA; float* nxt = FB;
    for (int j = 1; j < CH_; j++) {
        gemm64<GF_SADD><<<dim3(16, 16), 256>>>(cur + AP, HD_, Amat, nxt + AP,
                                               nullptr, Bu, nullptr, nullptr,
                                               HD_, HD_, j);
        float* t = cur; cur = nxt; nxt = t;
    }
    // after 31 steps, local endpoints F in cur (= FB)

    // 6) Hillis-Steele inclusive prefix over 64 chunks (6 rounds):
    //    F'_c = F_{c-s} @ P^s + F_c ; zero apron supplies F_{c<0} = 0.
    float* Pk = P0; float* Po = P1;
    for (int r = 0; r < 6; r++) {
        const int s = 1 << r;
        gemm64<GF_ADDM><<<dim3(16, 16), 256>>>(cur + AP - (size_t)16 * s * HD_, HD_,
                                               Pk, nxt + AP,
                                               nullptr, nullptr, nullptr, cur + AP,
                                               HD_, HD_, 0);
        float* t = cur; cur = nxt; nxt = t;
        if (r < 5) {
            gemm64<0><<<dim3(16,16),256>>>(Pk, HD_, Pk, Po, 0,0,0,0, HD_, HD_, 0);
            float* u = Pk; Pk = Po; Po = u;
        }
    }
    // inclusive prefix F in cur; exclusive prefix S_c = F_{c-1} at (cur + AP - 16*HD_)

    // 7) Phase 2: true recurrence per chunk from carry-in; scatter to d_out
    {
        const float* st = cur + AP - (size_t)16 * HD_;
        gemm64<GF_SADD | GF_SSTORE><<<dim3(16, 16), 256>>>(st, HD_, Amat, nxt + AP,
                                                           nullptr, Bu, outH, nullptr,
                                                           HD_, HD_, 0);
        float* t = cur; cur = nxt; nxt = t;
        for (int j = 1; j < CH_; j++) {
            gemm64<GF_SADD | GF_SSTORE><<<dim3(16, 16), 256>>>(cur + AP, HD_, Amat,
                                                               nxt + AP,
                                                               nullptr, Bu, outH, nullptr,
                                                               HD_, HD_, j);
            t = cur; cur = nxt; nxt = t;
        }
    }

    // 8) z = x[:, -1, :] @ W_res + b_res + H_seq_pre[:, -1, :]
    sgemm16<SF_BIAS | SF_ADD><<<16, 256>>>(x + (size_t)(SEQ_ - 1) * LIN_,
                                           (long)SEQ_ * LIN_,
                                           Wres, HD_, Z, HD_, bres,
                                           outH + (size_t)(SEQ_ - 1) * HD_,
                                           (long)SEQ_ * HD_, BATCH_, LIN_);
    // 9) LayerNorm
    ln16<<<BATCH_, 256>>>(Z, lng, lnb, HL);
    // 10) MLP head
    sgemm16<SF_BIAS | SF_RELU><<<FMLP_ / 64, 256>>>(HL, HD_, W1, FMLP_, T, FMLP_,
                                                    b1, nullptr, 0, BATCH_, HD_);
    sgemm16<SF_BIAS><<<HD_ / 64, 256>>>(T, FMLP_, W2, HD_, out0, HD_,
                                        b2, nullptr, 0, BATCH_, FMLP_);
}